// round 10
// baseline (speedup 1.0000x reference)
#include <cuda_runtime.h>
#include <math.h>
#include <stdint.h>

// Problem constants: B=2, S=2048, D=1024, H=16, DH=64, INNER=1024
#define BB   2
#define SS   2048
#define DD   1024
#define HH   16
#define DHD  64
#define MROWS (BB * SS)   // 4096 token rows

// Scratch (static device globals -- no allocations allowed)
__device__ float g_x  [(size_t)MROWS * DD];         // tf32-rounded x
__device__ float g_q  [(size_t)MROWS * DD];         // q (normalized+scaled+rounded)
__device__ float g_kv [(size_t)MROWS * 2 * DD];     // [k(normalized) | v] rounded
__device__ float g_o  [(size_t)MROWS * DD];         // attention output (tf32-rounded)
__device__ float g_wq [(size_t)DD * DD];            // tf32-rounded w_q
__device__ float g_wkv[(size_t)DD * 2 * DD];        // tf32-rounded w_kv
__device__ float g_wo [(size_t)DD * DD];            // tf32-rounded w_out

// ---------------------------------------------------------------------------
// helpers
// ---------------------------------------------------------------------------
__device__ __forceinline__ uint32_t smem_u32(const void* p) {
    uint32_t a;
    asm("{ .reg .u64 t; cvta.to.shared.u64 t, %1; cvt.u32.u64 %0, t; }" : "=r"(a) : "l"(p));
    return a;
}

__device__ __forceinline__ float tf32r(float x) {
    uint32_t u;
    asm("cvt.rna.tf32.f32 %0, %1;" : "=r"(u) : "f"(x));
    return __uint_as_float(u);
}

__device__ __forceinline__ void cp16(uint32_t dst, const void* src) {
    asm volatile("cp.async.cg.shared.global [%0], [%1], 16;" :: "r"(dst), "l"(src));
}
__device__ __forceinline__ void cp_commit() {
    asm volatile("cp.async.commit_group;" ::: "memory");
}
__device__ __forceinline__ void cp_wait0() {
    asm volatile("cp.async.wait_group 0;" ::: "memory");
}

__device__ __forceinline__ void mma_tf32(float* d, const uint32_t* a, const uint32_t* b) {
    asm volatile(
        "mma.sync.aligned.m16n8k8.row.col.f32.tf32.tf32.f32 "
        "{%0,%1,%2,%3}, {%4,%5,%6,%7}, {%8,%9}, {%0,%1,%2,%3};"
        : "+f"(d[0]), "+f"(d[1]), "+f"(d[2]), "+f"(d[3])
        : "r"(a[0]), "r"(a[1]), "r"(a[2]), "r"(a[3]), "r"(b[0]), "r"(b[1]));
}

// ldmatrix x4 (b16 view of tf32 data)
__device__ __forceinline__ void ldm_x4(uint32_t* r, uint32_t addr) {
    asm volatile("ldmatrix.sync.aligned.m8n8.x4.shared.b16 {%0,%1,%2,%3}, [%4];"
        : "=r"(r[0]), "=r"(r[1]), "=r"(r[2]), "=r"(r[3]) : "r"(addr));
}

// ---------------------------------------------------------------------------
// tf32 rounding kernels
// ---------------------------------------------------------------------------
__global__ void round_tf32(const float* __restrict__ in, float* __restrict__ out, int n4)
{
    int i = blockIdx.x * blockDim.x + threadIdx.x;
    if (i < n4) {
        float4 v = ((const float4*)in)[i];
        v.x = tf32r(v.x); v.y = tf32r(v.y); v.z = tf32r(v.z); v.w = tf32r(v.w);
        ((float4*)out)[i] = v;
    }
}

#define WQ4  (DD * DD / 4)
#define WKV4 (2 * DD * DD / 4)
__global__ void round_w(const float* __restrict__ wq,  float* __restrict__ owq,
                        const float* __restrict__ wkv, float* __restrict__ owkv,
                        const float* __restrict__ wo,  float* __restrict__ owo)
{
    int i = blockIdx.x * blockDim.x + threadIdx.x;
    const float4* src;
    float4* dst;
    int idx;
    if (i < WQ4)             { src = (const float4*)wq;  dst = (float4*)owq;  idx = i; }
    else if (i < WQ4 + WKV4) { src = (const float4*)wkv; dst = (float4*)owkv; idx = i - WQ4; }
    else                     { src = (const float4*)wo;  dst = (float4*)owo;  idx = i - WQ4 - WKV4; }
    float4 v = src[idx];
    v.x = tf32r(v.x); v.y = tf32r(v.y); v.z = tf32r(v.z); v.w = tf32r(v.w);
    dst[idx] = v;
}

// ---------------------------------------------------------------------------
// Shared GEMM tile config
// ---------------------------------------------------------------------------
#define GA_PITCH 36
#define GB_PITCH 136
#define GA_STG_F (128 * GA_PITCH)
#define GB_STG_F (32 * GB_PITCH)
#define GEMM_SMEM ((2 * GA_STG_F + 2 * GB_STG_F) * 4)

// ---------------------------------------------------------------------------
// Fused qkv projection GEMM: virtual N = 3072 over [w_q | w_kv].
// CTA cols (bn, 128 wide) lie wholly in one weight tensor.
// Epilogue: bn<DD -> q (L2-norm * exp(scale), round) -> g_q;
//           bn<2DD -> k (L2-norm, round) -> g_kv;  else v (round) -> g_kv.
// 3 CTAs/SM target (reg cap 85, smem 3x71.7KB = 215KB).
// ---------------------------------------------------------------------------
__global__ __launch_bounds__(256, 3) void mma_gemm_qkv(
    const float* __restrict__ A, const float* __restrict__ Wq,
    const float* __restrict__ Wkv, float* __restrict__ Cq,
    float* __restrict__ Ckv, const float* __restrict__ scale)
{
    extern __shared__ float smem[];
    float* sBf = smem + 2 * GA_STG_F;
    const uint32_t sbase = smem_u32(smem);

    const int t    = threadIdx.x;
    const int wid  = t >> 5, lane = t & 31;
    const int g    = lane >> 2, tg = lane & 3;
    const int wm   = wid >> 1, wn = wid & 1;
    const int bm   = blockIdx.y * 128;
    const int bn   = blockIdx.x * 128;
    const int K    = DD;

    const bool isQ = (bn < DD);
    const float* Bg = isQ ? (Wq + bn) : (Wkv + (bn - DD));
    const int Nb = isQ ? DD : 2 * DD;            // B row stride
    float* C = isQ ? Cq : Ckv;
    const int Nc = Nb;
    const int cb = isQ ? bn : bn - DD;           // output col base

    const float* Ag = A + (size_t)bm * K;

    const int arow = t >> 1,  acol = (t & 1) * 16;
    const int brow = t >> 3,  bcol = (t & 7) * 4;

    const uint32_t a_lm = (uint32_t)(((lane & 7) + 8 * ((lane >> 3) & 1)) * GA_PITCH * 4
                                     + (lane >> 4) * 16);

    const int nk = K / 32;

    auto loadStage = [&](int s, int kt) {
        uint32_t ad = sbase + (uint32_t)(s * GA_STG_F + arow * GA_PITCH + acol) * 4u;
        const float* as = Ag + (size_t)arow * K + kt * 32 + acol;
#pragma unroll
        for (int u = 0; u < 4; u++) cp16(ad + u * 16, as + u * 4);
        uint32_t bd = sbase + (uint32_t)((2 * GA_STG_F) + s * GB_STG_F + brow * GB_PITCH + bcol) * 4u;
        const float* bs = Bg + (size_t)(kt * 32 + brow) * Nb + bcol;
#pragma unroll
        for (int u = 0; u < 4; u++) cp16(bd + u * 128, bs + u * 32);
    };

    float acc[2][8][4];
#pragma unroll
    for (int i = 0; i < 2; i++)
#pragma unroll
        for (int j = 0; j < 8; j++)
#pragma unroll
            for (int c = 0; c < 4; c++) acc[i][j][c] = 0.f;

    loadStage(0, 0);
    cp_commit();

    for (int kt = 0; kt < nk; kt++) {
        cp_wait0();
        __syncthreads();

        if (kt + 1 < nk) {
            loadStage((kt + 1) & 1, kt + 1);
            cp_commit();
        }

        const uint32_t saA = sbase + (uint32_t)((kt & 1) * GA_STG_F) * 4u
                           + (uint32_t)(wm * 32 * GA_PITCH) * 4u + a_lm;
        const float* sb = sBf + (kt & 1) * GB_STG_F;

#pragma unroll
        for (int ks = 0; ks < 4; ks++) {
            uint32_t a[2][4];
            ldm_x4(a[0], saA + ks * 32);
            ldm_x4(a[1], saA + 16 * GA_PITCH * 4 + ks * 32);
            uint32_t b[8][2];
#pragma unroll
            for (int j = 0; j < 8; j++) {
                const int col = wn * 64 + j * 8 + g;
                b[j][0] = __float_as_uint(sb[(ks * 8 + tg    ) * GB_PITCH + col]);
                b[j][1] = __float_as_uint(sb[(ks * 8 + tg + 4) * GB_PITCH + col]);
            }
#pragma unroll
            for (int i = 0; i < 2; i++)
#pragma unroll
                for (int j = 0; j < 8; j++)
                    mma_tf32(acc[i][j], a[i], b[j]);
        }
    }

    // epilogue: per-head-row L2 norm (q and k halves) + tf32 round
    const int colBase = cb + wn * 64;
    const bool doNorm = isQ || (colBase < DD);   // k half of kv

#pragma unroll
    for (int i = 0; i < 2; i++) {
        const int row = bm + wm * 32 + i * 16 + g;
        float f0 = 1.f, f1 = 1.f;
        if (doNorm) {
            float ss0 = 0.f, ss1 = 0.f;
#pragma unroll
            for (int j = 0; j < 8; j++) {
                ss0 += acc[i][j][0] * acc[i][j][0] + acc[i][j][1] * acc[i][j][1];
                ss1 += acc[i][j][2] * acc[i][j][2] + acc[i][j][3] * acc[i][j][3];
            }
            ss0 += __shfl_xor_sync(0xffffffffu, ss0, 1);
            ss0 += __shfl_xor_sync(0xffffffffu, ss0, 2);
            ss1 += __shfl_xor_sync(0xffffffffu, ss1, 1);
            ss1 += __shfl_xor_sync(0xffffffffu, ss1, 2);
            f0 = 1.f / fmaxf(sqrtf(ss0), 1e-12f);
            f1 = 1.f / fmaxf(sqrtf(ss1), 1e-12f);
            if (isQ) {
                const float e = expf(scale[colBase >> 6]);
                f0 *= e;
                f1 *= e;
            }
        }
#pragma unroll
        for (int j = 0; j < 8; j++) {
            const int col = colBase + j * 8 + tg * 2;
            float2 v0, v1;
            v0.x = tf32r(acc[i][j][0] * f0); v0.y = tf32r(acc[i][j][1] * f0);
            v1.x = tf32r(acc[i][j][2] * f1); v1.y = tf32r(acc[i][j][3] * f1);
            *(float2*)(C + (size_t)row * Nc + col)       = v0;
            *(float2*)(C + (size_t)(row + 8) * Nc + col) = v1;
        }
    }
}

// ---------------------------------------------------------------------------
// Plain tf32 GEMM (out projection): C = A @ B + bias. Same tile config.
// ---------------------------------------------------------------------------
__global__ __launch_bounds__(256, 3) void mma_gemm(
    const float* __restrict__ A, const float* __restrict__ B,
    float* __restrict__ C, int N, int K, const float* __restrict__ bias)
{
    extern __shared__ float smem[];
    float* sBf = smem + 2 * GA_STG_F;
    const uint32_t sbase = smem_u32(smem);

    const int t    = threadIdx.x;
    const int wid  = t >> 5, lane = t & 31;
    const int g    = lane >> 2, tg = lane & 3;
    const int wm   = wid >> 1, wn = wid & 1;
    const int bm   = blockIdx.y * 128;
    const int bn   = blockIdx.x * 128;

    const float* Ag = A + (size_t)bm * K;
    const float* Bg = B + bn;

    const int arow = t >> 1,  acol = (t & 1) * 16;
    const int brow = t >> 3,  bcol = (t & 7) * 4;

    const uint32_t a_lm = (uint32_t)(((lane & 7) + 8 * ((lane >> 3) & 1)) * GA_PITCH * 4
                                     + (lane >> 4) * 16);

    const int nk = K / 32;

    auto loadStage = [&](int s, int kt) {
        uint32_t ad = sbase + (uint32_t)(s * GA_STG_F + arow * GA_PITCH + acol) * 4u;
        const float* as = Ag + (size_t)arow * K + kt * 32 + acol;
#pragma unroll
        for (int u = 0; u < 4; u++) cp16(ad + u * 16, as + u * 4);
        uint32_t bd = sbase + (uint32_t)((2 * GA_STG_F) + s * GB_STG_F + brow * GB_PITCH + bcol) * 4u;
        const float* bs = Bg + (size_t)(kt * 32 + brow) * N + bcol;
#pragma unroll
        for (int u = 0; u < 4; u++) cp16(bd + u * 128, bs + u * 32);
    };

    float acc[2][8][4];
#pragma unroll
    for (int i = 0; i < 2; i++)
#pragma unroll
        for (int j = 0; j < 8; j++)
#pragma unroll
            for (int c = 0; c < 4; c++) acc[i][j][c] = 0.f;

    loadStage(0, 0);
    cp_commit();

    for (int kt = 0; kt < nk; kt++) {
        cp_wait0();
        __syncthreads();

        if (kt + 1 < nk) {
            loadStage((kt + 1) & 1, kt + 1);
            cp_commit();
        }

        const uint32_t saA = sbase + (uint32_t)((kt & 1) * GA_STG_F) * 4u
                           + (uint32_t)(wm * 32 * GA_PITCH) * 4u + a_lm;
        const float* sb = sBf + (kt & 1) * GB_STG_F;

#pragma unroll
        for (int ks = 0; ks < 4; ks++) {
            uint32_t a[2][4];
            ldm_x4(a[0], saA + ks * 32);
            ldm_x4(a[1], saA + 16 * GA_PITCH * 4 + ks * 32);
            uint32_t b[8][2];
#pragma unroll
            for (int j = 0; j < 8; j++) {
                const int col = wn * 64 + j * 8 + g;
                b[j][0] = __float_as_uint(sb[(ks * 8 + tg    ) * GB_PITCH + col]);
                b[j][1] = __float_as_uint(sb[(ks * 8 + tg + 4) * GB_PITCH + col]);
            }
#pragma unroll
            for (int i = 0; i < 2; i++)
#pragma unroll
                for (int j = 0; j < 8; j++)
                    mma_tf32(acc[i][j], a[i], b[j]);
        }
    }

#pragma unroll
    for (int i = 0; i < 2; i++) {
        const int row = bm + wm * 32 + i * 16 + g;
#pragma unroll
        for (int j = 0; j < 8; j++) {
            const int col = bn + wn * 64 + j * 8 + tg * 2;
            float b0 = bias[col], b1 = bias[col + 1];
            float2 v0 = make_float2(acc[i][j][0] + b0, acc[i][j][1] + b1);
            float2 v1 = make_float2(acc[i][j][2] + b0, acc[i][j][3] + b1);
            *(float2*)(C + (size_t)row * N + col)       = v0;
            *(float2*)(C + (size_t)(row + 8) * N + col) = v1;
        }
    }
}

// ---------------------------------------------------------------------------
// Flash attention (validated R8): tf32 mma.sync + ldmatrix, cp.async 2-stage.
// ---------------------------------------------------------------------------
#define FQ  128
#define FKT 64
#define QP  68
#define KSP 68
#define VSP 72
#define KV_STG (FKT * KSP + FKT * VSP)
#define FLASH_SMEM ((FQ * QP + 2 * KV_STG) * 4)

__global__ __launch_bounds__(256) void flash_mma(
    const float* __restrict__ q, const float* __restrict__ kv, float* __restrict__ o)
{
    extern __shared__ float sm[];
    float* QsPs = sm;
    const uint32_t sbase = smem_u32(sm);
    const uint32_t stgBase = sbase + FQ * QP * 4u;

    const int qt = blockIdx.x, h = blockIdx.y, b = blockIdx.z;
    const int tid = threadIdx.x, wid = tid >> 5, lane = tid & 31;
    const int g = lane >> 2, tg = lane & 3;
    const int m0 = wid * 16;

    const float* qbase = q  + ((size_t)(b * SS) + qt * FQ) * DD + h * DHD;
    const float* kbase = kv + (size_t)(b * SS) * (2 * DD) + h * DHD;
    const float* vbase = kbase + DD;

    const int sr = tid >> 2, sc = (tid & 3) * 16;

    const uint32_t a_lm = (uint32_t)(((lane & 7) + 8 * ((lane >> 3) & 1)) * QP * 4
                                     + (lane >> 4) * 16);
    const uint32_t b_lm = (uint32_t)((lane & 7) * KSP * 4 + (lane >> 3) * 16);

    auto prefetchKV = [&](int s, int jt) {
        const float* krow = kbase + (size_t)(jt * FKT + sr) * (2 * DD) + sc;
        const float* vrow = vbase + (size_t)(jt * FKT + sr) * (2 * DD) + sc;
        uint32_t kd = stgBase + (uint32_t)(s * KV_STG + sr * KSP + sc) * 4u;
        uint32_t vd = stgBase + (uint32_t)(s * KV_STG + FKT * KSP + sr * VSP + sc) * 4u;
#pragma unroll
        for (int u = 0; u < 4; u++) {
            cp16(kd + u * 16, krow + u * 4);
            cp16(vd + u * 16, vrow + u * 4);
        }
    };

    prefetchKV(0, 0);
    cp_commit();

    {
        const int r = tid >> 1, c0 = (tid & 1) * 32;
#pragma unroll
        for (int u = 0; u < 8; u++) {
            float4 v = *(const float4*)(qbase + (size_t)r * DD + c0 + u * 4);
            *(float4*)&QsPs[r * QP + c0 + u * 4] = v;
        }
    }
    __syncthreads();

    const uint32_t qpAddr = sbase + (uint32_t)(m0 * QP) * 4u + a_lm;
    uint32_t qa[8][4];
#pragma unroll
    for (int ks = 0; ks < 8; ks++) ldm_x4(qa[ks], qpAddr + ks * 32);

    float l0 = 0.f, l1 = 0.f;
    float oacc[8][4];
#pragma unroll
    for (int j = 0; j < 8; j++)
#pragma unroll
        for (int c = 0; c < 4; c++) oacc[j][c] = 0.f;

    const int NT = SS / FKT;
    for (int jt = 0; jt < NT; jt++) {
        cp_wait0();
        __syncthreads();

        if (jt + 1 < NT) {
            prefetchKV((jt + 1) & 1, jt + 1);
            cp_commit();
        }

        const uint32_t ksAddr = stgBase + (uint32_t)((jt & 1) * KV_STG) * 4u + b_lm;
        const float* Vs = sm + FQ * QP + (jt & 1) * KV_STG + FKT * KSP;

        float sacc[8][4];
#pragma unroll
        for (int j = 0; j < 8; j++)
#pragma unroll
            for (int c = 0; c < 4; c++) sacc[j][c] = 0.f;

#pragma unroll
        for (int p = 0; p < 4; p++) {
#pragma unroll
            for (int j = 0; j < 8; j++) {
                uint32_t r[4];
                ldm_x4(r, ksAddr + (uint32_t)(j * 8 * KSP) * 4u + p * 64);
                mma_tf32(sacc[j], qa[2 * p],     r);
                mma_tf32(sacc[j], qa[2 * p + 1], r + 2);
            }
        }

        float rs0 = 0.f, rs1 = 0.f;
#pragma unroll
        for (int j = 0; j < 8; j++) {
            float p0 = tf32r(__expf(sacc[j][0]));
            float p1 = tf32r(__expf(sacc[j][1]));
            float p2 = tf32r(__expf(sacc[j][2]));
            float p3 = tf32r(__expf(sacc[j][3]));
            rs0 += p0 + p1;
            rs1 += p2 + p3;
            *(float2*)&QsPs[(m0 + g    ) * QP + j * 8 + 2 * tg] = make_float2(p0, p1);
            *(float2*)&QsPs[(m0 + g + 8) * QP + j * 8 + 2 * tg] = make_float2(p2, p3);
        }
        rs0 += __shfl_xor_sync(0xffffffffu, rs0, 1);
        rs0 += __shfl_xor_sync(0xffffffffu, rs0, 2);
        rs1 += __shfl_xor_sync(0xffffffffu, rs1, 1);
        rs1 += __shfl_xor_sync(0xffffffffu, rs1, 2);
        l0 += rs0;
        l1 += rs1;
        __syncwarp();

#pragma unroll
        for (int ks = 0; ks < 8; ks++) {
            uint32_t a[4];
            ldm_x4(a, qpAddr + ks * 32);
#pragma unroll
            for (int j = 0; j < 8; j++) {
                uint32_t bb[2];
                bb[0] = __float_as_uint(Vs[(ks * 8 + tg    ) * VSP + j * 8 + g]);
                bb[1] = __float_as_uint(Vs[(ks * 8 + tg + 4) * VSP + j * 8 + g]);
                mma_tf32(oacc[j], a, bb);
            }
        }
    }

    float* obase = o + ((size_t)(b * SS) + qt * FQ) * DD + h * DHD;
    const float inv0 = 1.f / l0, inv1 = 1.f / l1;
#pragma unroll
    for (int j = 0; j < 8; j++) {
        const int col = j * 8 + 2 * tg;
        *(float2*)(obase + (size_t)(m0 + g    ) * DD + col) =
            make_float2(tf32r(oacc[j][0] * inv0), tf32r(oacc[j][1] * inv0));
        *(float2*)(obase + (size_t)(m0 + g + 8) * DD + col) =
            make_float2(tf32r(oacc[j][2] * inv1), tf32r(oacc[j][3] * inv1));
    }
}

// ---------------------------------------------------------------------------
extern "C" void kernel_launch(void* const* d_in, const int* in_sizes, int n_in,
                              void* d_out, int out_size)
{
    const float* x     = (const float*)d_in[0];
    const float* w_q   = (const float*)d_in[1];
    const float* w_kv  = (const float*)d_in[2];
    const float* w_out = (const float*)d_in[3];
    const float* b_out = (const float*)d_in[4];
    const float* scale = (const float*)d_in[5];
    float* out = (float*)d_out;

    float *px, *pq, *pkv, *po, *pwq, *pwkv, *pwo;
    cudaGetSymbolAddress((void**)&px,   g_x);
    cudaGetSymbolAddress((void**)&pq,   g_q);
    cudaGetSymbolAddress((void**)&pkv,  g_kv);
    cudaGetSymbolAddress((void**)&po,   g_o);
    cudaGetSymbolAddress((void**)&pwq,  g_wq);
    cudaGetSymbolAddress((void**)&pwkv, g_wkv);
    cudaGetSymbolAddress((void**)&pwo,  g_wo);

    cudaFuncSetAttribute(flash_mma, cudaFuncAttributeMaxDynamicSharedMemorySize, FLASH_SMEM);
    cudaFuncSetAttribute(mma_gemm, cudaFuncAttributeMaxDynamicSharedMemorySize, GEMM_SMEM);
    cudaFuncSetAttribute(mma_gemm_qkv, cudaFuncAttributeMaxDynamicSharedMemorySize, GEMM_SMEM);

    const int T = 256;
    // launch 0: round x
    round_tf32<<<(MROWS * DD / 4 + T - 1) / T, T>>>(x, px, MROWS * DD / 4);
    // launch 1: round all weights
    round_w<<<(WQ4 + WKV4 + WQ4 + T - 1) / T, T>>>(w_q, pwq, w_kv, pwkv, w_out, pwo);

    // launch 2: fused q + kv projections (virtual N=3072, 768 CTAs)
    mma_gemm_qkv<<<dim3(3 * DD / 128, MROWS / 128), 256, GEMM_SMEM>>>(
        px, pwq, pwkv, pq, pkv, scale);

    // launch 3: attention
    flash_mma<<<dim3(SS / FQ, HH, BB), 256, FLASH_SMEM>>>(pq, pkv, po);

    // launch 4: out = g_o @ w_out + b_out
    mma_gemm<<<dim3(DD / 128, MROWS / 128), 256, GEMM_SMEM>>>(
        po, pwo, out, DD, DD, b_out);
}

// round 11
// speedup vs baseline: 1.1297x; 1.1297x over previous
#include <cuda_runtime.h>
#include <math.h>
#include <stdint.h>

// Problem constants: B=2, S=2048, D=1024, H=16, DH=64, INNER=1024
#define BB   2
#define SS   2048
#define DD   1024
#define HH   16
#define DHD  64
#define MROWS (BB * SS)   // 4096 token rows

// Scratch (static device globals -- no allocations allowed)
__device__ float g_x  [(size_t)MROWS * DD];         // tf32-rounded x
__device__ float g_q  [(size_t)MROWS * DD];         // q (normalized+scaled+rounded)
__device__ float g_kv [(size_t)MROWS * 2 * DD];     // [k(normalized) | v] rounded
__device__ float g_o  [(size_t)MROWS * DD];         // attention output (tf32-rounded)
__device__ float g_wq [(size_t)DD * DD];            // tf32-rounded w_q
__device__ float g_wkv[(size_t)DD * 2 * DD];        // tf32-rounded w_kv
__device__ float g_wo [(size_t)DD * DD];            // tf32-rounded w_out

// ---------------------------------------------------------------------------
// helpers
// ---------------------------------------------------------------------------
__device__ __forceinline__ uint32_t smem_u32(const void* p) {
    uint32_t a;
    asm("{ .reg .u64 t; cvta.to.shared.u64 t, %1; cvt.u32.u64 %0, t; }" : "=r"(a) : "l"(p));
    return a;
}

__device__ __forceinline__ float tf32r(float x) {
    uint32_t u;
    asm("cvt.rna.tf32.f32 %0, %1;" : "=r"(u) : "f"(x));
    return __uint_as_float(u);
}

__device__ __forceinline__ void cp16(uint32_t dst, const void* src) {
    asm volatile("cp.async.cg.shared.global [%0], [%1], 16;" :: "r"(dst), "l"(src));
}
__device__ __forceinline__ void cp_commit() {
    asm volatile("cp.async.commit_group;" ::: "memory");
}
__device__ __forceinline__ void cp_wait0() {
    asm volatile("cp.async.wait_group 0;" ::: "memory");
}

__device__ __forceinline__ void mma_tf32(float* d, const uint32_t* a, const uint32_t* b) {
    asm volatile(
        "mma.sync.aligned.m16n8k8.row.col.f32.tf32.tf32.f32 "
        "{%0,%1,%2,%3}, {%4,%5,%6,%7}, {%8,%9}, {%0,%1,%2,%3};"
        : "+f"(d[0]), "+f"(d[1]), "+f"(d[2]), "+f"(d[3])
        : "r"(a[0]), "r"(a[1]), "r"(a[2]), "r"(a[3]), "r"(b[0]), "r"(b[1]));
}

// ldmatrix x4 (b16 view of tf32 data)
__device__ __forceinline__ void ldm_x4(uint32_t* r, uint32_t addr) {
    asm volatile("ldmatrix.sync.aligned.m8n8.x4.shared.b16 {%0,%1,%2,%3}, [%4];"
        : "=r"(r[0]), "=r"(r[1]), "=r"(r[2]), "=r"(r[3]) : "r"(addr));
}

// ---------------------------------------------------------------------------
// tf32 rounding kernels
// ---------------------------------------------------------------------------
__global__ void round_tf32(const float* __restrict__ in, float* __restrict__ out, int n4)
{
    int i = blockIdx.x * blockDim.x + threadIdx.x;
    if (i < n4) {
        float4 v = ((const float4*)in)[i];
        v.x = tf32r(v.x); v.y = tf32r(v.y); v.z = tf32r(v.z); v.w = tf32r(v.w);
        ((float4*)out)[i] = v;
    }
}

#define WQ4  (DD * DD / 4)
#define WKV4 (2 * DD * DD / 4)
__global__ void round_w(const float* __restrict__ wq,  float* __restrict__ owq,
                        const float* __restrict__ wkv, float* __restrict__ owkv,
                        const float* __restrict__ wo,  float* __restrict__ owo)
{
    int i = blockIdx.x * blockDim.x + threadIdx.x;
    const float4* src;
    float4* dst;
    int idx;
    if (i < WQ4)             { src = (const float4*)wq;  dst = (float4*)owq;  idx = i; }
    else if (i < WQ4 + WKV4) { src = (const float4*)wkv; dst = (float4*)owkv; idx = i - WQ4; }
    else                     { src = (const float4*)wo;  dst = (float4*)owo;  idx = i - WQ4 - WKV4; }
    float4 v = src[idx];
    v.x = tf32r(v.x); v.y = tf32r(v.y); v.z = tf32r(v.z); v.w = tf32r(v.w);
    dst[idx] = v;
}

// ---------------------------------------------------------------------------
// Shared GEMM tile config
// ---------------------------------------------------------------------------
#define GA_PITCH 36
#define GB_PITCH 136
#define GA_STG_F (128 * GA_PITCH)
#define GB_STG_F (32 * GB_PITCH)
#define GEMM_SMEM ((2 * GA_STG_F + 2 * GB_STG_F) * 4)

// ---------------------------------------------------------------------------
// Fused qkv projection GEMM (R9 fusion, natural regs restored).
// ---------------------------------------------------------------------------
__global__ __launch_bounds__(256) void mma_gemm_qkv(
    const float* __restrict__ A, const float* __restrict__ Wq,
    const float* __restrict__ Wkv, float* __restrict__ Cq,
    float* __restrict__ Ckv, const float* __restrict__ scale)
{
    extern __shared__ float smem[];
    float* sBf = smem + 2 * GA_STG_F;
    const uint32_t sbase = smem_u32(smem);

    const int t    = threadIdx.x;
    const int wid  = t >> 5, lane = t & 31;
    const int g    = lane >> 2, tg = lane & 3;
    const int wm   = wid >> 1, wn = wid & 1;
    const int bm   = blockIdx.y * 128;
    const int bn   = blockIdx.x * 128;
    const int K    = DD;

    const bool isQ = (bn < DD);
    const float* Bg = isQ ? (Wq + bn) : (Wkv + (bn - DD));
    const int Nb = isQ ? DD : 2 * DD;
    float* C = isQ ? Cq : Ckv;
    const int cb = isQ ? bn : bn - DD;

    const float* Ag = A + (size_t)bm * K;

    const int arow = t >> 1,  acol = (t & 1) * 16;
    const int brow = t >> 3,  bcol = (t & 7) * 4;

    const uint32_t a_lm = (uint32_t)(((lane & 7) + 8 * ((lane >> 3) & 1)) * GA_PITCH * 4
                                     + (lane >> 4) * 16);

    const int nk = K / 32;

    auto loadStage = [&](int s, int kt) {
        uint32_t ad = sbase + (uint32_t)(s * GA_STG_F + arow * GA_PITCH + acol) * 4u;
        const float* as = Ag + (size_t)arow * K + kt * 32 + acol;
#pragma unroll
        for (int u = 0; u < 4; u++) cp16(ad + u * 16, as + u * 4);
        uint32_t bd = sbase + (uint32_t)((2 * GA_STG_F) + s * GB_STG_F + brow * GB_PITCH + bcol) * 4u;
        const float* bs = Bg + (size_t)(kt * 32 + brow) * Nb + bcol;
#pragma unroll
        for (int u = 0; u < 4; u++) cp16(bd + u * 128, bs + u * 32);
    };

    float acc[2][8][4];
#pragma unroll
    for (int i = 0; i < 2; i++)
#pragma unroll
        for (int j = 0; j < 8; j++)
#pragma unroll
            for (int c = 0; c < 4; c++) acc[i][j][c] = 0.f;

    loadStage(0, 0);
    cp_commit();

    for (int kt = 0; kt < nk; kt++) {
        cp_wait0();
        __syncthreads();

        if (kt + 1 < nk) {
            loadStage((kt + 1) & 1, kt + 1);
            cp_commit();
        }

        const uint32_t saA = sbase + (uint32_t)((kt & 1) * GA_STG_F) * 4u
                           + (uint32_t)(wm * 32 * GA_PITCH) * 4u + a_lm;
        const float* sb = sBf + (kt & 1) * GB_STG_F;

#pragma unroll
        for (int ks = 0; ks < 4; ks++) {
            uint32_t a[2][4];
            ldm_x4(a[0], saA + ks * 32);
            ldm_x4(a[1], saA + 16 * GA_PITCH * 4 + ks * 32);
            uint32_t b[8][2];
#pragma unroll
            for (int j = 0; j < 8; j++) {
                const int col = wn * 64 + j * 8 + g;
                b[j][0] = __float_as_uint(sb[(ks * 8 + tg    ) * GB_PITCH + col]);
                b[j][1] = __float_as_uint(sb[(ks * 8 + tg + 4) * GB_PITCH + col]);
            }
#pragma unroll
            for (int i = 0; i < 2; i++)
#pragma unroll
                for (int j = 0; j < 8; j++)
                    mma_tf32(acc[i][j], a[i], b[j]);
        }
    }

    const int colBase = cb + wn * 64;
    const bool doNorm = isQ || (colBase < DD);

#pragma unroll
    for (int i = 0; i < 2; i++) {
        const int row = bm + wm * 32 + i * 16 + g;
        float f0 = 1.f, f1 = 1.f;
        if (doNorm) {
            float ss0 = 0.f, ss1 = 0.f;
#pragma unroll
            for (int j = 0; j < 8; j++) {
                ss0 += acc[i][j][0] * acc[i][j][0] + acc[i][j][1] * acc[i][j][1];
                ss1 += acc[i][j][2] * acc[i][j][2] + acc[i][j][3] * acc[i][j][3];
            }
            ss0 += __shfl_xor_sync(0xffffffffu, ss0, 1);
            ss0 += __shfl_xor_sync(0xffffffffu, ss0, 2);
            ss1 += __shfl_xor_sync(0xffffffffu, ss1, 1);
            ss1 += __shfl_xor_sync(0xffffffffu, ss1, 2);
            f0 = 1.f / fmaxf(sqrtf(ss0), 1e-12f);
            f1 = 1.f / fmaxf(sqrtf(ss1), 1e-12f);
            if (isQ) {
                const float e = expf(scale[colBase >> 6]);
                f0 *= e;
                f1 *= e;
            }
        }
#pragma unroll
        for (int j = 0; j < 8; j++) {
            const int col = colBase + j * 8 + tg * 2;
            float2 v0, v1;
            v0.x = tf32r(acc[i][j][0] * f0); v0.y = tf32r(acc[i][j][1] * f0);
            v1.x = tf32r(acc[i][j][2] * f1); v1.y = tf32r(acc[i][j][3] * f1);
            *(float2*)(C + (size_t)row * Nb + col)       = v0;
            *(float2*)(C + (size_t)(row + 8) * Nb + col) = v1;
        }
    }
}

// ---------------------------------------------------------------------------
// Plain tf32 GEMM (out projection).
// ---------------------------------------------------------------------------
__global__ __launch_bounds__(256) void mma_gemm(
    const float* __restrict__ A, const float* __restrict__ B,
    float* __restrict__ C, int N, int K, const float* __restrict__ bias)
{
    extern __shared__ float smem[];
    float* sBf = smem + 2 * GA_STG_F;
    const uint32_t sbase = smem_u32(smem);

    const int t    = threadIdx.x;
    const int wid  = t >> 5, lane = t & 31;
    const int g    = lane >> 2, tg = lane & 3;
    const int wm   = wid >> 1, wn = wid & 1;
    const int bm   = blockIdx.y * 128;
    const int bn   = blockIdx.x * 128;

    const float* Ag = A + (size_t)bm * K;
    const float* Bg = B + bn;

    const int arow = t >> 1,  acol = (t & 1) * 16;
    const int brow = t >> 3,  bcol = (t & 7) * 4;

    const uint32_t a_lm = (uint32_t)(((lane & 7) + 8 * ((lane >> 3) & 1)) * GA_PITCH * 4
                                     + (lane >> 4) * 16);

    const int nk = K / 32;

    auto loadStage = [&](int s, int kt) {
        uint32_t ad = sbase + (uint32_t)(s * GA_STG_F + arow * GA_PITCH + acol) * 4u;
        const float* as = Ag + (size_t)arow * K + kt * 32 + acol;
#pragma unroll
        for (int u = 0; u < 4; u++) cp16(ad + u * 16, as + u * 4);
        uint32_t bd = sbase + (uint32_t)((2 * GA_STG_F) + s * GB_STG_F + brow * GB_PITCH + bcol) * 4u;
        const float* bs = Bg + (size_t)(kt * 32 + brow) * N + bcol;
#pragma unroll
        for (int u = 0; u < 4; u++) cp16(bd + u * 128, bs + u * 32);
    };

    float acc[2][8][4];
#pragma unroll
    for (int i = 0; i < 2; i++)
#pragma unroll
        for (int j = 0; j < 8; j++)
#pragma unroll
            for (int c = 0; c < 4; c++) acc[i][j][c] = 0.f;

    loadStage(0, 0);
    cp_commit();

    for (int kt = 0; kt < nk; kt++) {
        cp_wait0();
        __syncthreads();

        if (kt + 1 < nk) {
            loadStage((kt + 1) & 1, kt + 1);
            cp_commit();
        }

        const uint32_t saA = sbase + (uint32_t)((kt & 1) * GA_STG_F) * 4u
                           + (uint32_t)(wm * 32 * GA_PITCH) * 4u + a_lm;
        const float* sb = sBf + (kt & 1) * GB_STG_F;

#pragma unroll
        for (int ks = 0; ks < 4; ks++) {
            uint32_t a[2][4];
            ldm_x4(a[0], saA + ks * 32);
            ldm_x4(a[1], saA + 16 * GA_PITCH * 4 + ks * 32);
            uint32_t b[8][2];
#pragma unroll
            for (int j = 0; j < 8; j++) {
                const int col = wn * 64 + j * 8 + g;
                b[j][0] = __float_as_uint(sb[(ks * 8 + tg    ) * GB_PITCH + col]);
                b[j][1] = __float_as_uint(sb[(ks * 8 + tg + 4) * GB_PITCH + col]);
            }
#pragma unroll
            for (int i = 0; i < 2; i++)
#pragma unroll
                for (int j = 0; j < 8; j++)
                    mma_tf32(acc[i][j], a[i], b[j]);
        }
    }

#pragma unroll
    for (int i = 0; i < 2; i++) {
        const int row = bm + wm * 32 + i * 16 + g;
#pragma unroll
        for (int j = 0; j < 8; j++) {
            const int col = bn + wn * 64 + j * 8 + tg * 2;
            float b0 = bias[col], b1 = bias[col + 1];
            float2 v0 = make_float2(acc[i][j][0] + b0, acc[i][j][1] + b1);
            float2 v1 = make_float2(acc[i][j][2] + b0, acc[i][j][3] + b1);
            *(float2*)(C + (size_t)row * N + col)       = v0;
            *(float2*)(C + (size_t)(row + 8) * N + col) = v1;
        }
    }
}

// ---------------------------------------------------------------------------
// Flash attention v3: per-j fused softmax+PV, P via intra-quad shuffles
// (no Ps smem, no sacc/P register arrays) -> regs ~100, 2 CTAs/SM.
// CTA: 128 q-rows, 8 warps x 16 rows, 64-key tiles, cp.async 2-stage K/V.
// ---------------------------------------------------------------------------
#define FQ  128
#define FKT 64
#define QP  68
#define KSP 68
#define VSP 72
#define KV_STG (FKT * KSP + FKT * VSP)
#define FLASH_SMEM ((FQ * QP + 2 * KV_STG) * 4)

__global__ __launch_bounds__(256, 2) void flash_mma(
    const float* __restrict__ q, const float* __restrict__ kv, float* __restrict__ o)
{
    extern __shared__ float sm[];
    float* Qs = sm;                        // prologue staging only
    const uint32_t sbase = smem_u32(sm);
    const uint32_t stgBase = sbase + FQ * QP * 4u;

    const int qt = blockIdx.x, h = blockIdx.y, b = blockIdx.z;
    const int tid = threadIdx.x, wid = tid >> 5, lane = tid & 31;
    const int g = lane >> 2, tg = lane & 3;
    const int m0 = wid * 16;
    const int srcLo = (lane & ~3) | (tg >> 1);   // quad lane holding col tg (and tg parity slot)
    const int srcHi = srcLo + 2;                 // quad lane holding col tg+4

    const float* qbase = q  + ((size_t)(b * SS) + qt * FQ) * DD + h * DHD;
    const float* kbase = kv + (size_t)(b * SS) * (2 * DD) + h * DHD;
    const float* vbase = kbase + DD;

    const int sr = tid >> 2, sc = (tid & 3) * 16;

    const uint32_t a_lm = (uint32_t)(((lane & 7) + 8 * ((lane >> 3) & 1)) * QP * 4
                                     + (lane >> 4) * 16);
    const uint32_t b_lm = (uint32_t)((lane & 7) * KSP * 4 + (lane >> 3) * 16);

    auto prefetchKV = [&](int s, int jt) {
        const float* krow = kbase + (size_t)(jt * FKT + sr) * (2 * DD) + sc;
        const float* vrow = vbase + (size_t)(jt * FKT + sr) * (2 * DD) + sc;
        uint32_t kd = stgBase + (uint32_t)(s * KV_STG + sr * KSP + sc) * 4u;
        uint32_t vd = stgBase + (uint32_t)(s * KV_STG + FKT * KSP + sr * VSP + sc) * 4u;
#pragma unroll
        for (int u = 0; u < 4; u++) {
            cp16(kd + u * 16, krow + u * 4);
            cp16(vd + u * 16, vrow + u * 4);
        }
    };

    prefetchKV(0, 0);
    cp_commit();

    // Stage Q, hoist fragments via ldmatrix (Qs unused afterwards)
    {
        const int r = tid >> 1, c0 = (tid & 1) * 32;
#pragma unroll
        for (int u = 0; u < 8; u++) {
            float4 v = *(const float4*)(qbase + (size_t)r * DD + c0 + u * 4);
            *(float4*)&Qs[r * QP + c0 + u * 4] = v;
        }
    }
    __syncthreads();

    const uint32_t qpAddr = sbase + (uint32_t)(m0 * QP) * 4u + a_lm;
    uint32_t qa[8][4];
#pragma unroll
    for (int ks = 0; ks < 8; ks++) ldm_x4(qa[ks], qpAddr + ks * 32);

    float l0 = 0.f, l1 = 0.f;
    float oacc[8][4];
#pragma unroll
    for (int j = 0; j < 8; j++)
#pragma unroll
        for (int c = 0; c < 4; c++) oacc[j][c] = 0.f;

    const int NT = SS / FKT;
    for (int jt = 0; jt < NT; jt++) {
        cp_wait0();
        __syncthreads();   // stage jt visible; all warps done with stage jt-1

        if (jt + 1 < NT) {
            prefetchKV((jt + 1) & 1, jt + 1);
            cp_commit();
        }

        const uint32_t ksAddr = stgBase + (uint32_t)((jt & 1) * KV_STG) * 4u + b_lm;
        const float* Vs = sm + FQ * QP + (jt & 1) * KV_STG + FKT * KSP;

        float rs0 = 0.f, rs1 = 0.f;

#pragma unroll
        for (int j = 0; j < 8; j++) {
            // GEMM1 for key-block j: S[16x8]
            float sacc[4] = {0.f, 0.f, 0.f, 0.f};
#pragma unroll
            for (int p = 0; p < 4; p++) {
                uint32_t r[4];
                ldm_x4(r, ksAddr + (uint32_t)(j * 8 * KSP) * 4u + p * 64);
                mma_tf32(sacc, qa[2 * p],     r);
                mma_tf32(sacc, qa[2 * p + 1], r + 2);
            }

            // softmax numerator (max-free; |logit| <= exp(scale) ~ 0.0455)
            float p0 = tf32r(__expf(sacc[0]));   // (g,    2tg)
            float p1 = tf32r(__expf(sacc[1]));   // (g,    2tg+1)
            float p2 = tf32r(__expf(sacc[2]));   // (g+8,  2tg)
            float p3 = tf32r(__expf(sacc[3]));   // (g+8,  2tg+1)
            rs0 += p0 + p1;
            rs1 += p2 + p3;

            // C-frag -> A-frag via intra-quad shuffles (bit-exact remap)
            float u0 = __shfl_sync(0xffffffffu, p0, srcLo);
            float u1 = __shfl_sync(0xffffffffu, p1, srcLo);
            float u2 = __shfl_sync(0xffffffffu, p0, srcHi);
            float u3 = __shfl_sync(0xffffffffu, p1, srcHi);
            float w0 = __shfl_sync(0xffffffffu, p2, srcLo);
            float w1 = __shfl_sync(0xffffffffu, p3, srcLo);
            float w2 = __shfl_sync(0xffffffffu, p2, srcHi);
            float w3 = __shfl_sync(0xffffffffu, p3, srcHi);
            uint32_t a[4];
            a[0] = __float_as_uint((tg & 1) ? u1 : u0);   // P(g,   tg)
            a[1] = __float_as_uint((tg & 1) ? w1 : w0);   // P(g+8, tg)
            a[2] = __float_as_uint((tg & 1) ? u3 : u2);   // P(g,   tg+4)
            a[3] = __float_as_uint((tg & 1) ? w3 : w2);   // P(g+8, tg+4)

            // GEMM2 for k-block j: O[16x64] += P_j @ V_j
#pragma unroll
            for (int jj = 0; jj < 8; jj++) {
                uint32_t bb[2];
                bb[0] = __float_as_uint(Vs[(j * 8 + tg    ) * VSP + jj * 8 + g]);
                bb[1] = __float_as_uint(Vs[(j * 8 + tg + 4) * VSP + jj * 8 + g]);
                mma_tf32(oacc[jj], a, bb);
            }
        }

        rs0 += __shfl_xor_sync(0xffffffffu, rs0, 1);
        rs0 += __shfl_xor_sync(0xffffffffu, rs0, 2);
        rs1 += __shfl_xor_sync(0xffffffffu, rs1, 1);
        rs1 += __shfl_xor_sync(0xffffffffu, rs1, 2);
        l0 += rs0;
        l1 += rs1;
    }

    // Epilogue: softmax divide + tf32 round
    float* obase = o + ((size_t)(b * SS) + qt * FQ) * DD + h * DHD;
    const float inv0 = 1.f / l0, inv1 = 1.f / l1;
#pragma unroll
    for (int j = 0; j < 8; j++) {
        const int col = j * 8 + 2 * tg;
        *(float2*)(obase + (size_t)(m0 + g    ) * DD + col) =
            make_float2(tf32r(oacc[j][0] * inv0), tf32r(oacc[j][1] * inv0));
        *(float2*)(obase + (size_t)(m0 + g + 8) * DD + col) =
            make_float2(tf32r(oacc[j][2] * inv1), tf32r(oacc[j][3] * inv1));
    }
}

// ---------------------------------------------------------------------------
extern "C" void kernel_launch(void* const* d_in, const int* in_sizes, int n_in,
                              void* d_out, int out_size)
{
    const float* x     = (const float*)d_in[0];
    const float* w_q   = (const float*)d_in[1];
    const float* w_kv  = (const float*)d_in[2];
    const float* w_out = (const float*)d_in[3];
    const float* b_out = (const float*)d_in[4];
    const float* scale = (const float*)d_in[5];
    float* out = (float*)d_out;

    float *px, *pq, *pkv, *po, *pwq, *pwkv, *pwo;
    cudaGetSymbolAddress((void**)&px,   g_x);
    cudaGetSymbolAddress((void**)&pq,   g_q);
    cudaGetSymbolAddress((void**)&pkv,  g_kv);
    cudaGetSymbolAddress((void**)&po,   g_o);
    cudaGetSymbolAddress((void**)&pwq,  g_wq);
    cudaGetSymbolAddress((void**)&pwkv, g_wkv);
    cudaGetSymbolAddress((void**)&pwo,  g_wo);

    cudaFuncSetAttribute(flash_mma, cudaFuncAttributeMaxDynamicSharedMemorySize, FLASH_SMEM);
    cudaFuncSetAttribute(mma_gemm, cudaFuncAttributeMaxDynamicSharedMemorySize, GEMM_SMEM);
    cudaFuncSetAttribute(mma_gemm_qkv, cudaFuncAttributeMaxDynamicSharedMemorySize, GEMM_SMEM);

    const int T = 256;
    // launch 0: round x
    round_tf32<<<(MROWS * DD / 4 + T - 1) / T, T>>>(x, px, MROWS * DD / 4);
    // launch 1: round all weights
    round_w<<<(WQ4 + WKV4 + WQ4 + T - 1) / T, T>>>(w_q, pwq, w_kv, pwkv, w_out, pwo);

    // launch 2: fused q + kv projections
    mma_gemm_qkv<<<dim3(3 * DD / 128, MROWS / 128), 256, GEMM_SMEM>>>(
        px, pwq, pwkv, pq, pkv, scale);

    // launch 3: attention
    flash_mma<<<dim3(SS / FQ, HH, BB), 256, FLASH_SMEM>>>(pq, pkv, po);

    // launch 4: out = g_o @ w_out + b_out
    mma_gemm<<<dim3(DD / 128, MROWS / 128), 256, GEMM_SMEM>>>(
        po, pwo, out, DD, DD, b_out);
}